// round 1
// baseline (speedup 1.0000x reference)
#include <cuda_runtime.h>

// PairwiseL1Loss: x,y [256][4096] fp32.
// mseX[i][j] = mean_k |x[i][k]-x[j][k]|, same for y.
// out[i] = -sum_j mseX[i][j]*mseY[i][j]
//
// Strategy: tile pair matrix 16x16 per CTA (grid 16x16 = 256 CTAs),
// 256 threads = 1 pair/thread, k staged through smem in 128-float chunks.
// Deterministic: partials to __device__ scratch, second kernel reduces.

#define BB 256
#define DD 4096
#define TI 16
#define KC 128
#define NTILE (BB / TI)          // 16 j-tiles
#define KPAD 4                   // smem row stride = KC+4 floats (2-phase LDS.128)

__device__ float g_partial[BB * NTILE];   // [i][j_tile]

__global__ __launch_bounds__(256, 2)
void pairwise_l1_tile_kernel(const float* __restrict__ x,
                             const float* __restrict__ y)
{
    __shared__ float sxi[TI][KC + KPAD];
    __shared__ float sxj[TI][KC + KPAD];
    __shared__ float syi[TI][KC + KPAD];
    __shared__ float syj[TI][KC + KPAD];

    const int tid = threadIdx.x;
    const int ti  = tid >> 4;     // 0..15  (i within tile)
    const int tj  = tid & 15;     // 0..15  (j within tile)
    const int iBase = blockIdx.y * TI;
    const int jBase = blockIdx.x * TI;

    // 8 independent accumulator chains (FADD lat=4, rt=2 -> plenty of ILP)
    float ax0 = 0.f, ax1 = 0.f, ax2 = 0.f, ax3 = 0.f;
    float ay0 = 0.f, ay1 = 0.f, ay2 = 0.f, ay3 = 0.f;

    for (int kb = 0; kb < DD; kb += KC) {
        __syncthreads();   // protect smem from previous chunk's readers

        // Stage chunk: 4 arrays x 16 rows x 128 floats. 512 float4 per array,
        // 256 threads -> 2 float4 per thread per array. Coalesced along k.
        #pragma unroll
        for (int v = tid; v < (TI * KC / 4); v += 256) {
            const int row = v >> 5;        // v / 32
            const int c4  = v & 31;        // float4 index within row
            const float4 vxi = *(const float4*)(x + (size_t)(iBase + row) * DD + kb + (c4 << 2));
            const float4 vxj = *(const float4*)(x + (size_t)(jBase + row) * DD + kb + (c4 << 2));
            const float4 vyi = *(const float4*)(y + (size_t)(iBase + row) * DD + kb + (c4 << 2));
            const float4 vyj = *(const float4*)(y + (size_t)(jBase + row) * DD + kb + (c4 << 2));
            *(float4*)&sxi[row][c4 << 2] = vxi;
            *(float4*)&sxj[row][c4 << 2] = vxj;
            *(float4*)&syi[row][c4 << 2] = vyi;
            *(float4*)&syj[row][c4 << 2] = vyj;
        }
        __syncthreads();

        #pragma unroll
        for (int kk = 0; kk < KC; kk += 4) {
            const float4 xi = *(const float4*)&sxi[ti][kk];
            const float4 xj = *(const float4*)&sxj[tj][kk];
            const float4 yi = *(const float4*)&syi[ti][kk];
            const float4 yj = *(const float4*)&syj[tj][kk];
            ax0 += fabsf(xi.x - xj.x);
            ax1 += fabsf(xi.y - xj.y);
            ax2 += fabsf(xi.z - xj.z);
            ax3 += fabsf(xi.w - xj.w);
            ay0 += fabsf(yi.x - yj.x);
            ay1 += fabsf(yi.y - yj.y);
            ay2 += fabsf(yi.z - yj.z);
            ay3 += fabsf(yi.w - yj.w);
        }
    }

    const float sx = (ax0 + ax1) + (ax2 + ax3);
    const float sy = (ay0 + ay1) + (ay2 + ay3);
    float prod = sx * sy;

    // Reduce over tj (16 consecutive lanes = half-warp; xor offsets < 16
    // stay inside the half-warp).
    #pragma unroll
    for (int off = 8; off > 0; off >>= 1)
        prod += __shfl_xor_sync(0xffffffffu, prod, off);

    if (tj == 0)
        g_partial[(iBase + ti) * NTILE + blockIdx.x] = prod;
}

__global__ void pairwise_l1_reduce_kernel(float* __restrict__ out)
{
    const int i = blockIdx.x * blockDim.x + threadIdx.x;
    if (i < BB) {
        float s = 0.f;
        #pragma unroll
        for (int t = 0; t < NTILE; t++)
            s += g_partial[i * NTILE + t];
        // mean over D twice -> 1/(D*D); 1/16777216 is exact in fp32.
        out[i] = -s * (1.0f / ((float)DD * (float)DD));
    }
}

extern "C" void kernel_launch(void* const* d_in, const int* in_sizes, int n_in,
                              void* d_out, int out_size)
{
    const float* x = (const float*)d_in[0];
    const float* y = (const float*)d_in[1];
    float* out = (float*)d_out;

    dim3 grid(NTILE, NTILE);
    pairwise_l1_tile_kernel<<<grid, 256>>>(x, y);
    pairwise_l1_reduce_kernel<<<1, 256>>>(out);
}

// round 3
// speedup vs baseline: 2.3945x; 2.3945x over previous
#include <cuda_runtime.h>

// PairwiseL1Loss: x,y [256][4096] fp32.
// out[i] = -(1/D^2) * sum_j (sum_k|x_i-x_j|) * (sum_k|y_i-y_j|)
//
// Key identity: sum_k|x_i-x_j| = 2*sum_k max(x_ik,x_jk) - S_i - S_j,
// S_i = sum_k x_ik. Inner loop is ONE FMNMX per element-pair (ALU pipe).
//
// PS : row sums Sx[256], Sy[256].
// PA : symmetric 64x64 pair tiles (10 of 16), k-split x64, 4x4 register
//      tiling, swizzled smem -> per-pair partial (mx,my) max-sums per chunk.
// PB1: sum k-chunks, apply identity, form product per pair.
// PB2: row/col sums per tile (unique writers -> deterministic).
// PC : final 4-way sum, scale, negate.

#define BB 256
#define DD 4096
#define TILE 64
#define NT (BB / TILE)                 // 4 tiles per side
#define NPT 10                         // upper-tri tile count
#define KSPLIT 64
#define KPER (DD / KSPLIT)             // 64 k per CTA
#define KC 32                          // smem stage depth (rows exactly 128B)

__device__ float2 g_part[NPT * KSPLIT * TILE * TILE];   // [pt][kc][pair] ~21MB
__device__ float  g_prod[NPT * TILE * TILE];            // [pt][pair]
__device__ float  g_final[BB * NT];                     // [i][other_tile]
__device__ float  g_Sx[BB];
__device__ float  g_Sy[BB];

__constant__ int c_bi[NPT] = {0,0,0,0,1,1,1,2,2,3};
__constant__ int c_bj[NPT] = {0,1,2,3,1,2,3,2,3,3};

// accumulate max(u,v) over 4 components
#define MAX4(acc, u, v)                          \
    acc += fmaxf((u).x, (v).x);                  \
    acc += fmaxf((u).y, (v).y);                  \
    acc += fmaxf((u).z, (v).z);                  \
    acc += fmaxf((u).w, (v).w);

// ---------- PS: row sums ----------
__global__ void ps_kernel(const float* __restrict__ x,
                          const float* __restrict__ y)
{
    // grid 256 (one row), block 128
    const int row = blockIdx.x;
    const int tid = threadIdx.x;
    float sx = 0.f, sy = 0.f;
    const float4* px = (const float4*)(x + (size_t)row * DD);
    const float4* py = (const float4*)(y + (size_t)row * DD);
    #pragma unroll
    for (int v = tid; v < DD / 4; v += 128) {
        const float4 a = px[v];
        const float4 b = py[v];
        sx += (a.x + a.y) + (a.z + a.w);
        sy += (b.x + b.y) + (b.z + b.w);
    }
    #pragma unroll
    for (int off = 16; off > 0; off >>= 1) {
        sx += __shfl_xor_sync(0xffffffffu, sx, off);
        sy += __shfl_xor_sync(0xffffffffu, sy, off);
    }
    __shared__ float wx[4], wy[4];
    if ((tid & 31) == 0) { wx[tid >> 5] = sx; wy[tid >> 5] = sy; }
    __syncthreads();
    if (tid == 0) {
        g_Sx[row] = (wx[0] + wx[1]) + (wx[2] + wx[3]);
        g_Sy[row] = (wy[0] + wy[1]) + (wy[2] + wy[3]);
    }
}

// ---------- PA: max-sum pair tiles ----------
__global__ __launch_bounds__(256, 2)
void pa_kernel(const float* __restrict__ x, const float* __restrict__ y)
{
    // [row][8 quads], quad index XOR-swizzled by (row>>2)&7
    __shared__ float4 sxi[TILE * 8];
    __shared__ float4 sxj[TILE * 8];
    __shared__ float4 syi[TILE * 8];
    __shared__ float4 syj[TILE * 8];

    const int pt = blockIdx.x / KSPLIT;
    const int kc = blockIdx.x % KSPLIT;
    const int bi = c_bi[pt], bj = c_bj[pt];
    const int iBase = bi * TILE, jBase = bj * TILE;
    const int tid = threadIdx.x;
    const int ti = tid >> 4;           // 0..15
    const int tj = tid & 15;           // 0..15

    float mx[4][4], my[4][4];
    #pragma unroll
    for (int a = 0; a < 4; a++)
        #pragma unroll
        for (int b = 0; b < 4; b++) { mx[a][b] = 0.f; my[a][b] = 0.f; }

    const int tik = ti & 7;
    const int tjk = tj & 7;

    for (int ks = 0; ks < KPER; ks += KC) {
        const int kBase = kc * KPER + ks;
        __syncthreads();

        // stage 4 arrays: 64 rows x 32 floats each = 512 float4 per array
        #pragma unroll
        for (int v = tid; v < TILE * 8; v += 256) {
            const int r = v >> 3;
            const int q = v & 7;
            const int sq = q ^ ((r >> 2) & 7);
            const size_t offI = (size_t)(iBase + r) * DD + kBase;
            const size_t offJ = (size_t)(jBase + r) * DD + kBase;
            sxi[r * 8 + sq] = ((const float4*)(x + offI))[q];
            sxj[r * 8 + sq] = ((const float4*)(x + offJ))[q];
            syi[r * 8 + sq] = ((const float4*)(y + offI))[q];
            syj[r * 8 + sq] = ((const float4*)(y + offJ))[q];
        }
        __syncthreads();

        const float4* pxi = sxi + 4 * ti * 8;
        const float4* pxj = sxj + 4 * tj * 8;
        const float4* pyi = syi + 4 * ti * 8;
        const float4* pyj = syj + 4 * tj * 8;

        #pragma unroll
        for (int kq = 0; kq < 8; kq++) {
            const int qi = kq ^ tik;
            const int qj = kq ^ tjk;
            {
                const float4 u0 = pxi[0 * 8 + qi];
                const float4 u1 = pxi[1 * 8 + qi];
                const float4 u2 = pxi[2 * 8 + qi];
                const float4 u3 = pxi[3 * 8 + qi];
                const float4 v0 = pxj[0 * 8 + qj];
                const float4 v1 = pxj[1 * 8 + qj];
                const float4 v2 = pxj[2 * 8 + qj];
                const float4 v3 = pxj[3 * 8 + qj];
                MAX4(mx[0][0], u0, v0); MAX4(mx[0][1], u0, v1);
                MAX4(mx[0][2], u0, v2); MAX4(mx[0][3], u0, v3);
                MAX4(mx[1][0], u1, v0); MAX4(mx[1][1], u1, v1);
                MAX4(mx[1][2], u1, v2); MAX4(mx[1][3], u1, v3);
                MAX4(mx[2][0], u2, v0); MAX4(mx[2][1], u2, v1);
                MAX4(mx[2][2], u2, v2); MAX4(mx[2][3], u2, v3);
                MAX4(mx[3][0], u3, v0); MAX4(mx[3][1], u3, v1);
                MAX4(mx[3][2], u3, v2); MAX4(mx[3][3], u3, v3);
            }
            {
                const float4 u0 = pyi[0 * 8 + qi];
                const float4 u1 = pyi[1 * 8 + qi];
                const float4 u2 = pyi[2 * 8 + qi];
                const float4 u3 = pyi[3 * 8 + qi];
                const float4 v0 = pyj[0 * 8 + qj];
                const float4 v1 = pyj[1 * 8 + qj];
                const float4 v2 = pyj[2 * 8 + qj];
                const float4 v3 = pyj[3 * 8 + qj];
                MAX4(my[0][0], u0, v0); MAX4(my[0][1], u0, v1);
                MAX4(my[0][2], u0, v2); MAX4(my[0][3], u0, v3);
                MAX4(my[1][0], u1, v0); MAX4(my[1][1], u1, v1);
                MAX4(my[1][2], u1, v2); MAX4(my[1][3], u1, v3);
                MAX4(my[2][0], u2, v0); MAX4(my[2][1], u2, v1);
                MAX4(my[2][2], u2, v2); MAX4(my[2][3], u2, v3);
                MAX4(my[3][0], u3, v0); MAX4(my[3][1], u3, v1);
                MAX4(my[3][2], u3, v2); MAX4(my[3][3], u3, v3);
            }
        }
    }

    float2* gp = g_part + ((size_t)pt * KSPLIT + kc) * (TILE * TILE);
    #pragma unroll
    for (int a = 0; a < 4; a++)
        #pragma unroll
        for (int b = 0; b < 4; b++)
            gp[(4 * ti + a) * TILE + (4 * tj + b)] = make_float2(mx[a][b], my[a][b]);
}

// ---------- PB1: sum k-chunks, apply identity, product ----------
__global__ void pb1_kernel()
{
    const int pt  = blockIdx.x >> 4;
    const int seg = blockIdx.x & 15;
    const int p   = seg * 256 + threadIdx.x;
    const float2* gp = g_part + (size_t)pt * KSPLIT * (TILE * TILE);
    float mx = 0.f, my = 0.f;
    #pragma unroll
    for (int kcc = 0; kcc < KSPLIT; kcc++) {
        const float2 v = gp[(size_t)kcc * (TILE * TILE) + p];
        mx += v.x;
        my += v.y;
    }
    const int bi = c_bi[pt], bj = c_bj[pt];
    const int ig = bi * TILE + (p >> 6);
    const int jg = bj * TILE + (p & 63);
    const float sx = 2.0f * mx - g_Sx[ig] - g_Sx[jg];
    const float sy = 2.0f * my - g_Sy[ig] - g_Sy[jg];
    g_prod[pt * (TILE * TILE) + p] = sx * sy;
}

// ---------- PB2: row & column sums per tile ----------
__global__ void pb2_kernel()
{
    __shared__ float sprod[TILE][TILE + 1];
    const int pt = blockIdx.x;
    const int bi = c_bi[pt], bj = c_bj[pt];
    const int tid = threadIdx.x;

    #pragma unroll
    for (int w = 0; w < 16; w++) {
        const int p = tid + 256 * w;
        sprod[p >> 6][p & 63] = g_prod[pt * (TILE * TILE) + p];
    }
    __syncthreads();

    if (tid < TILE) {                       // row sums -> out rows of tile bi
        float s = 0.f;
        #pragma unroll
        for (int j = 0; j < TILE; j++) s += sprod[tid][j];
        g_final[(bi * TILE + tid) * NT + bj] = s;
    } else if (tid >= 128 && tid < 128 + TILE) {
        if (bi != bj) {                     // col sums -> out rows of tile bj
            const int c = tid - 128;
            float s = 0.f;
            #pragma unroll
            for (int i = 0; i < TILE; i++) s += sprod[i][c];
            g_final[(bj * TILE + c) * NT + bi] = s;
        }
    }
}

// ---------- PC: finalize ----------
__global__ void pc_kernel(float* __restrict__ out)
{
    const int i = threadIdx.x;   // 256 threads, 1 block
    const float s = g_final[i * NT + 0] + g_final[i * NT + 1]
                  + g_final[i * NT + 2] + g_final[i * NT + 3];
    out[i] = -s * (1.0f / ((float)DD * (float)DD));
}

extern "C" void kernel_launch(void* const* d_in, const int* in_sizes, int n_in,
                              void* d_out, int out_size)
{
    const float* x = (const float*)d_in[0];
    const float* y = (const float*)d_in[1];
    float* out = (float*)d_out;

    ps_kernel<<<BB, 128>>>(x, y);
    pa_kernel<<<NPT * KSPLIT, 256>>>(x, y);
    pb1_kernel<<<NPT * 16, 256>>>();
    pb2_kernel<<<NPT, 256>>>();
    pc_kernel<<<1, 256>>>(out);
}

// round 5
// speedup vs baseline: 2.8432x; 1.1874x over previous
#include <cuda_runtime.h>

// PairwiseL1Loss: x,y [256][4096] fp32.
// out[i] = -(1/D^2) * sum_j (sum_k|x_i-x_j|) * (sum_k|y_i-y_j|)
//
// Identity: sum_k|x_i-x_j| = 2*sum_k max(x_ik,x_jk) - S_i - S_j.
//
// PS : row sums Sx[256], Sy[256].
// PA : 32x32 pair tiles, upper-tri (36 of 64), k-split x16 -> grid 576,
//      occ 4 -> single wave. 2x2 reg tile/thread, swizzled smem.
// E1 : per tile-slab: sum k-chunks, identity, product, row sums + col partials.
// E2 : final combine, scale, negate.

#define BB 256
#define DD 4096
#define TILE 32
#define NT (BB / TILE)                 // 8 tiles per side
#define NPT 36                         // upper-tri tile count
#define KSPLIT 16
#define KPER (DD / KSPLIT)             // 256 k per CTA
#define KC 32                          // smem stage depth (rows exactly 128B)
#define NSTAGE (KPER / KC)             // 8

// [pt][kc][row*16 + colpair] : {mx0, my0, mx1, my1}
__device__ float4 g_part[NPT * KSPLIT * TILE * (TILE / 2)];   // ~4.7MB
__device__ float  g_final[BB * NT];                            // row-sum contribs
__device__ float  g_colpart[NPT * 4 * TILE];                   // col partials per 8-row seg
__device__ float  g_Sx[BB];
__device__ float  g_Sy[BB];

__constant__ int c_bi[NPT] = {0,0,0,0,0,0,0,0, 1,1,1,1,1,1,1, 2,2,2,2,2,2,
                              3,3,3,3,3, 4,4,4,4, 5,5,5, 6,6, 7};
__constant__ int c_bj[NPT] = {0,1,2,3,4,5,6,7, 1,2,3,4,5,6,7, 2,3,4,5,6,7,
                              3,4,5,6,7, 4,5,6,7, 5,6,7, 6,7, 7};

#define MAX4(acc, u, v)                          \
    acc += fmaxf((u).x, (v).x);                  \
    acc += fmaxf((u).y, (v).y);                  \
    acc += fmaxf((u).z, (v).z);                  \
    acc += fmaxf((u).w, (v).w);

// ---------- PS: row sums ----------
__global__ void ps_kernel(const float* __restrict__ x,
                          const float* __restrict__ y)
{
    const int row = blockIdx.x;
    const int tid = threadIdx.x;
    float sx = 0.f, sy = 0.f;
    const float4* px = (const float4*)(x + (size_t)row * DD);
    const float4* py = (const float4*)(y + (size_t)row * DD);
    #pragma unroll
    for (int v = tid; v < DD / 4; v += 128) {
        const float4 a = px[v];
        const float4 b = py[v];
        sx += (a.x + a.y) + (a.z + a.w);
        sy += (b.x + b.y) + (b.z + b.w);
    }
    #pragma unroll
    for (int off = 16; off > 0; off >>= 1) {
        sx += __shfl_xor_sync(0xffffffffu, sx, off);
        sy += __shfl_xor_sync(0xffffffffu, sy, off);
    }
    __shared__ float wx[4], wy[4];
    if ((tid & 31) == 0) { wx[tid >> 5] = sx; wy[tid >> 5] = sy; }
    __syncthreads();
    if (tid == 0) {
        g_Sx[row] = (wx[0] + wx[1]) + (wx[2] + wx[3]);
        g_Sy[row] = (wy[0] + wy[1]) + (wy[2] + wy[3]);
    }
}

// ---------- PA: max-sum pair tiles ----------
__global__ __launch_bounds__(256, 4)
void pa_kernel(const float* __restrict__ x, const float* __restrict__ y)
{
    // [row][8 quads], quad swizzled by (row>>1)&7
    __shared__ float4 sxi[TILE * 8];
    __shared__ float4 sxj[TILE * 8];
    __shared__ float4 syi[TILE * 8];
    __shared__ float4 syj[TILE * 8];

    const int pt = blockIdx.x / KSPLIT;
    const int kc = blockIdx.x % KSPLIT;
    const int bi = c_bi[pt], bj = c_bj[pt];
    const int iBase = bi * TILE, jBase = bj * TILE;
    const int tid = threadIdx.x;
    const int ti = tid >> 4;           // 0..15 -> rows 2ti, 2ti+1
    const int tj = tid & 15;           // 0..15 -> cols 2tj, 2tj+1

    float mx00 = 0.f, mx01 = 0.f, mx10 = 0.f, mx11 = 0.f;
    float my00 = 0.f, my01 = 0.f, my10 = 0.f, my11 = 0.f;

    const int tik = ti & 7;
    const int tjk = tj & 7;
    // staging indices: one float4 per thread per array
    const int sr = tid >> 3;           // 0..31
    const int sq = tid & 7;
    const int ssw = sr * 8 + (sq ^ ((sr >> 1) & 7));

    for (int st = 0; st < NSTAGE; st++) {
        const int kBase = kc * KPER + st * KC;
        __syncthreads();
        {
            const size_t offI = (size_t)(iBase + sr) * DD + kBase;
            const size_t offJ = (size_t)(jBase + sr) * DD + kBase;
            sxi[ssw] = ((const float4*)(x + offI))[sq];
            sxj[ssw] = ((const float4*)(x + offJ))[sq];
            syi[ssw] = ((const float4*)(y + offI))[sq];
            syj[ssw] = ((const float4*)(y + offJ))[sq];
        }
        __syncthreads();

        #pragma unroll
        for (int kq = 0; kq < 8; kq++) {
            const int qi = kq ^ tik;
            const int qj = kq ^ tjk;
            {
                const float4 u0 = sxi[(2 * ti    ) * 8 + qi];
                const float4 u1 = sxi[(2 * ti + 1) * 8 + qi];
                const float4 v0 = sxj[(2 * tj    ) * 8 + qj];
                const float4 v1 = sxj[(2 * tj + 1) * 8 + qj];
                MAX4(mx00, u0, v0); MAX4(mx01, u0, v1);
                MAX4(mx10, u1, v0); MAX4(mx11, u1, v1);
            }
            {
                const float4 u0 = syi[(2 * ti    ) * 8 + qi];
                const float4 u1 = syi[(2 * ti + 1) * 8 + qi];
                const float4 v0 = syj[(2 * tj    ) * 8 + qj];
                const float4 v1 = syj[(2 * tj + 1) * 8 + qj];
                MAX4(my00, u0, v0); MAX4(my01, u0, v1);
                MAX4(my10, u1, v0); MAX4(my11, u1, v1);
            }
        }
    }

    // [pt][kc][row*16 + colpair] = {mx(c0), my(c0), mx(c1), my(c1)}
    float4* gp = g_part + ((size_t)pt * KSPLIT + kc) * (TILE * (TILE / 2));
    gp[(2 * ti    ) * 16 + tj] = make_float4(mx00, my00, mx01, my01);
    gp[(2 * ti + 1) * 16 + tj] = make_float4(mx10, my10, mx11, my11);
}

// ---------- E1: k-chunk sum + identity + product + row/col reductions ----------
// grid = NPT*4, block = 128. Each CTA: one 8-row slab of one tile.
__global__ void e1_kernel()
{
    __shared__ float sp[8][TILE + 1];

    const int pt  = blockIdx.x >> 2;
    const int seg = blockIdx.x & 3;
    const int bi = c_bi[pt], bj = c_bj[pt];
    const int t = threadIdx.x;
    const int rloc = t >> 4;           // 0..7
    const int cp   = t & 15;           // col pair 0..15
    const int r = seg * 8 + rloc;
    const int ig = bi * TILE + r;
    const int j0 = bj * TILE + 2 * cp;

    const float4* gp = g_part + (size_t)pt * KSPLIT * (TILE * (TILE / 2))
                              + r * 16 + cp;
    float4 m = make_float4(0.f, 0.f, 0.f, 0.f);
    #pragma unroll
    for (int kcc = 0; kcc < KSPLIT; kcc++) {
        const float4 v = gp[(size_t)kcc * (TILE * (TILE / 2))];
        m.x += v.x; m.y += v.y; m.z += v.z; m.w += v.w;
    }
    const float Sxi = g_Sx[ig], Syi = g_Sy[ig];
    const float sx0 = 2.0f * m.x - Sxi - g_Sx[j0];
    const float sy0 = 2.0f * m.y - Syi - g_Sy[j0];
    const float sx1 = 2.0f * m.z - Sxi - g_Sx[j0 + 1];
    const float sy1 = 2.0f * m.w - Syi - g_Sy[j0 + 1];
    const float p0 = sx0 * sy0;
    const float p1 = sx1 * sy1;

    // row sum over 16 lanes (cp) of this rloc
    float rs = p0 + p1;
    #pragma unroll
    for (int off = 8; off > 0; off >>= 1)
        rs += __shfl_xor_sync(0xffffffffu, rs, off);
    if (cp == 0)
        g_final[ig * NT + bj] = rs;

    // col partials over the 8 rows of this slab
    sp[rloc][2 * cp]     = p0;
    sp[rloc][2 * cp + 1] = p1;
    __syncthreads();
    if (t < TILE) {
        float cs = 0.f;
        #pragma unroll
        for (int rr = 0; rr < 8; rr++) cs += sp[rr][t];
        g_colpart[(pt * 4 + seg) * TILE + t] = cs;
    }
}

// ---------- E2: final combine ----------
__global__ void e2_kernel(float* __restrict__ out)
{
    const int i = threadIdx.x;          // 256 threads, 1 block
    const int bi = i >> 5;              // tile of row i
    const int c  = i & 31;              // col within tile
    float s = 0.f;
    // row-sum contributions: tiles (bi, t), t >= bi
    #pragma unroll
    for (int t2 = 0; t2 < NT; t2++)
        if (t2 >= bi) s += g_final[i * NT + t2];
    // col-sum contributions: tiles (a, bi), a < bi
    for (int a = 0; a < bi; a++) {
        const int pt = a * NT - (a * (a - 1)) / 2 + (bi - a);
        #pragma unroll
        for (int seg = 0; seg < 4; seg++)
            s += g_colpart[(pt * 4 + seg) * TILE + c];
    }
    out[i] = -s * (1.0f / ((float)DD * (float)DD));
}

extern "C" void kernel_launch(void* const* d_in, const int* in_sizes, int n_in,
                              void* d_out, int out_size)
{
    const float* x = (const float*)d_in[0];
    const float* y = (const float*)d_in[1];
    float* out = (float*)d_out;

    ps_kernel<<<BB, 128>>>(x, y);
    pa_kernel<<<NPT * KSPLIT, 256>>>(x, y);
    e1_kernel<<<NPT * 4, 128>>>();
    e2_kernel<<<1, 256>>>(out);
}